// round 1
// baseline (speedup 1.0000x reference)
#include <cuda_runtime.h>

#define NPIX 4096
#define CIN  512
#define B    4

// Scratch (device globals — allocation-free per harness rules)
__device__ float g_qk[(size_t)B * 128 * NPIX];            // q rows 0-63, k rows 64-127
__device__ float g_v[(size_t)B * CIN * NPIX];             // 32 MB
__device__ float g_attn[(size_t)B * NPIX * NPIX];         // 256 MB

// ---------------------------------------------------------------------------
// proj: y[b, row_off+o, n] = sum_c W[o,c] * x[b,c,n] + bias[o]
// Tiles: 64(o) x 64(n), K-step 16. 256 threads, 4x4 per thread.
// ---------------------------------------------------------------------------
__global__ __launch_bounds__(256)
void proj_kernel(const float* __restrict__ W, const float* __restrict__ bias,
                 const float* __restrict__ x, float* __restrict__ y,
                 int ybatch, int row_off)
{
    __shared__ float Ws[64][16];     // [o][k]
    __shared__ float Xs[16][64];     // [k][n]
    const int b  = blockIdx.z;
    const int n0 = blockIdx.x * 64;
    const int o0 = blockIdx.y * 64;
    const int tid = threadIdx.x;
    const int tx = tid & 15;         // n / 4
    const int ty = tid >> 4;         // o / 4
    float acc[4][4] = {};
    const float* xb = x + (size_t)b * CIN * NPIX;

    for (int c0 = 0; c0 < CIN; c0 += 16) {
        int idx = tid;
        #pragma unroll
        for (int t = 0; t < 4; t++) {            // 64x16 W tile
            int r = idx >> 4, k = idx & 15;
            Ws[r][k] = W[(size_t)(o0 + r) * CIN + c0 + k];
            idx += 256;
        }
        idx = tid;
        #pragma unroll
        for (int t = 0; t < 4; t++) {            // 16x64 x tile (coalesced in n)
            int k = idx >> 6, nn = idx & 63;
            Xs[k][nn] = xb[(size_t)(c0 + k) * NPIX + n0 + nn];
            idx += 256;
        }
        __syncthreads();
        #pragma unroll
        for (int kk = 0; kk < 16; kk++) {
            float xv[4], wv[4];
            #pragma unroll
            for (int j = 0; j < 4; j++) xv[j] = Xs[kk][tx * 4 + j];
            #pragma unroll
            for (int i = 0; i < 4; i++) wv[i] = Ws[ty * 4 + i][kk];
            #pragma unroll
            for (int i = 0; i < 4; i++)
                #pragma unroll
                for (int j = 0; j < 4; j++)
                    acc[i][j] += wv[i] * xv[j];
        }
        __syncthreads();
    }

    float* yb = y + (size_t)b * ybatch + (size_t)row_off * NPIX;
    #pragma unroll
    for (int i = 0; i < 4; i++) {
        float bo = bias[o0 + ty * 4 + i];
        #pragma unroll
        for (int j = 0; j < 4; j++)
            yb[(size_t)(o0 + ty * 4 + i) * NPIX + n0 + tx * 4 + j] = acc[i][j] + bo;
    }
}

// ---------------------------------------------------------------------------
// scores: S[b,m,n] = sum_d q[b,d,m] * k[b,d,n]   (K = 64, one shot)
// Tiles: 64(m) x 64(n). 256 threads, 4x4 per thread.
// ---------------------------------------------------------------------------
__global__ __launch_bounds__(256)
void scores_kernel()
{
    __shared__ float Qs[64][64];     // [d][m]
    __shared__ float Ks[64][64];     // [d][n]
    const int b  = blockIdx.z;
    const int n0 = blockIdx.x * 64;
    const int m0 = blockIdx.y * 64;
    const int tid = threadIdx.x;
    const int tx = tid & 15;         // n / 4
    const int ty = tid >> 4;         // m / 4
    const float* q = g_qk + (size_t)b * 128 * NPIX;
    const float* k = q + (size_t)64 * NPIX;

    int idx = tid;
    #pragma unroll
    for (int t = 0; t < 16; t++) {               // 64x64 tiles, coalesced
        int d = idx >> 6, c = idx & 63;
        Qs[d][c] = q[(size_t)d * NPIX + m0 + c];
        Ks[d][c] = k[(size_t)d * NPIX + n0 + c];
        idx += 256;
    }
    __syncthreads();

    float acc[4][4] = {};
    #pragma unroll 16
    for (int d = 0; d < 64; d++) {
        float qv[4], kv[4];
        #pragma unroll
        for (int i = 0; i < 4; i++) qv[i] = Qs[d][ty * 4 + i];
        #pragma unroll
        for (int j = 0; j < 4; j++) kv[j] = Ks[d][tx * 4 + j];
        #pragma unroll
        for (int i = 0; i < 4; i++)
            #pragma unroll
            for (int j = 0; j < 4; j++)
                acc[i][j] += qv[i] * kv[j];
    }

    float* S = g_attn + ((size_t)b * NPIX + m0) * NPIX + n0;
    #pragma unroll
    for (int i = 0; i < 4; i++)
        #pragma unroll
        for (int j = 0; j < 4; j++)
            S[(size_t)(ty * 4 + i) * NPIX + tx * 4 + j] = acc[i][j];
}

// ---------------------------------------------------------------------------
// softmax over last axis, in place. One CTA per row, 16 elems/thread in regs.
// ---------------------------------------------------------------------------
__global__ __launch_bounds__(256)
void softmax_kernel()
{
    __shared__ float red[256];
    const int m = blockIdx.x, b = blockIdx.y;
    float* p = g_attn + ((size_t)b * NPIX + m) * NPIX;
    const int tid = threadIdx.x;

    float r[16];
    float mx = -1e30f;
    #pragma unroll
    for (int t = 0; t < 16; t++) {
        r[t] = p[tid + t * 256];
        mx = fmaxf(mx, r[t]);
    }
    red[tid] = mx;
    __syncthreads();
    for (int s = 128; s > 0; s >>= 1) {
        if (tid < s) red[tid] = fmaxf(red[tid], red[tid + s]);
        __syncthreads();
    }
    mx = red[0];
    __syncthreads();

    float sum = 0.f;
    #pragma unroll
    for (int t = 0; t < 16; t++) {
        r[t] = __expf(r[t] - mx);
        sum += r[t];
    }
    red[tid] = sum;
    __syncthreads();
    for (int s = 128; s > 0; s >>= 1) {
        if (tid < s) red[tid] += red[tid + s];
        __syncthreads();
    }
    float inv = 1.0f / red[0];

    #pragma unroll
    for (int t = 0; t < 16; t++)
        p[tid + t * 256] = r[t] * inv;
}

// ---------------------------------------------------------------------------
// out[b,c,m] = sum_n v[b,c,n] * attn[b,m,n] + x[b,c,m]
// Tiles: 64(c) x 64(m), K-step 32 over n. 256 threads, 4x4 per thread.
// ---------------------------------------------------------------------------
__global__ __launch_bounds__(256)
void out_kernel(const float* __restrict__ x, float* __restrict__ out)
{
    __shared__ float Vs[64][32];     // [c][n]
    __shared__ float As[32][65];     // [n][m]  (pad to keep writes conflict-free)
    const int b  = blockIdx.z;
    const int m0 = blockIdx.x * 64;
    const int c0 = blockIdx.y * 64;
    const int tid = threadIdx.x;
    const int tx = tid & 15;         // m / 4
    const int ty = tid >> 4;         // c / 4
    float acc[4][4] = {};
    const float* vb = g_v    + (size_t)b * CIN * NPIX;
    const float* ab = g_attn + (size_t)b * NPIX * NPIX;

    for (int n0 = 0; n0 < NPIX; n0 += 32) {
        int idx = tid;
        #pragma unroll
        for (int t = 0; t < 8; t++) {            // 64x32 v tile (coalesced in n)
            int cc = idx >> 5, kk2 = idx & 31;
            Vs[cc][kk2] = vb[(size_t)(c0 + cc) * NPIX + n0 + kk2];
            idx += 256;
        }
        idx = tid;
        #pragma unroll
        for (int t = 0; t < 8; t++) {            // 64x32 attn tile, transposed into [n][m]
            int mm = idx >> 5, kk2 = idx & 31;
            As[kk2][mm] = ab[(size_t)(m0 + mm) * NPIX + n0 + kk2];
            idx += 256;
        }
        __syncthreads();
        #pragma unroll
        for (int kk = 0; kk < 32; kk++) {
            float vv[4], av[4];
            #pragma unroll
            for (int i = 0; i < 4; i++) vv[i] = Vs[ty * 4 + i][kk];
            #pragma unroll
            for (int j = 0; j < 4; j++) av[j] = As[kk][tx * 4 + j];
            #pragma unroll
            for (int i = 0; i < 4; i++)
                #pragma unroll
                for (int j = 0; j < 4; j++)
                    acc[i][j] += vv[i] * av[j];
        }
        __syncthreads();
    }

    const float* xb = x + (size_t)b * CIN * NPIX;
    float* ob = out + (size_t)b * CIN * NPIX;
    #pragma unroll
    for (int i = 0; i < 4; i++)
        #pragma unroll
        for (int j = 0; j < 4; j++) {
            size_t off = (size_t)(c0 + ty * 4 + i) * NPIX + m0 + tx * 4 + j;
            ob[off] = acc[i][j] + xb[off];
        }
}

// ---------------------------------------------------------------------------
extern "C" void kernel_launch(void* const* d_in, const int* in_sizes, int n_in,
                              void* d_out, int out_size)
{
    const float* x  = (const float*)d_in[0];
    const float* Wq = (const float*)d_in[1];
    const float* bq = (const float*)d_in[2];
    const float* Wk = (const float*)d_in[3];
    const float* bk = (const float*)d_in[4];
    const float* Wv = (const float*)d_in[5];
    const float* bv = (const float*)d_in[6];
    float* out = (float*)d_out;

    float *qk, *v;
    cudaGetSymbolAddress((void**)&qk, g_qk);
    cudaGetSymbolAddress((void**)&v,  g_v);

    dim3 blk(256);
    proj_kernel<<<dim3(NPIX / 64, 1, B), blk>>>(Wq, bq, x, qk, 128 * NPIX, 0);
    proj_kernel<<<dim3(NPIX / 64, 1, B), blk>>>(Wk, bk, x, qk, 128 * NPIX, 64);
    proj_kernel<<<dim3(NPIX / 64, CIN / 64, B), blk>>>(Wv, bv, x, v, CIN * NPIX, 0);
    scores_kernel<<<dim3(NPIX / 64, NPIX / 64, B), blk>>>();
    softmax_kernel<<<dim3(NPIX, B), blk>>>();
    out_kernel<<<dim3(NPIX / 64, CIN / 64, B), blk>>>(x, out);
}